// round 1
// baseline (speedup 1.0000x reference)
#include <cuda_runtime.h>
#include <math.h>

#define HH   256
#define LL   5
#define TT   1000
#define BBATCH 128
#define NTHREADS 640   // 128 threads per layer * 5 layers

__device__ __forceinline__ float tanhapx(float x) {
    float r;
    asm("tanh.approx.f32 %0, %1;" : "=f"(r) : "f"(x));
    return r;
}

__global__ __launch_bounds__(NTHREADS, 1)
void lstm_wave_kernel(const float* __restrict__ x,
                      const float* __restrict__ Wih,
                      const float* __restrict__ Whh,
                      const float* __restrict__ bih,
                      const float* __restrict__ bhh,
                      const float* __restrict__ Whr,
                      const float* __restrict__ W1,
                      const float* __restrict__ b1,
                      const float* __restrict__ W2,
                      const float* __restrict__ b2,
                      const float* __restrict__ W3,
                      const float* __restrict__ b3,
                      const float* __restrict__ W4,
                      const float* __restrict__ b4,
                      float* __restrict__ out)
{
    __shared__ __align__(16) float xbuf[TT];
    __shared__ __align__(16) float hout[TT];
    __shared__ float part[2 * LL * 4];      // [parity][layer][warp-in-layer]
    __shared__ float a1[104], a2[104], a3[104];

    const int tid  = threadIdx.x;
    const int b    = blockIdx.x;
    const int l    = tid >> 7;        // layer: tid / 128
    const int j    = tid & 127;       // thread within layer
    const int w    = j >> 5;          // warp within layer (0..3)
    const int lane = j & 31;

    // ---- load per-thread weights (2 channels x 4 gates) ----
    // gate order: i, f, g, o. sigmoid(x) = 0.5*tanh(0.5x)+0.5 -> fold 0.5 into
    // weights for gates i, f, o.
    float wI[2][4], wH[2][4], bS[2][4], wR[2];
#pragma unroll
    for (int ch = 0; ch < 2; ++ch) {
        int h = j + ch * 128;
#pragma unroll
        for (int g = 0; g < 4; ++g) {
            int idx = l * 1024 + g * 256 + h;
            float s = (g == 2) ? 1.0f : 0.5f;
            wI[ch][g] = Wih[idx] * s;
            wH[ch][g] = Whh[idx] * s;
            bS[ch][g] = (bih[idx] + bhh[idx]) * s;
        }
        wR[ch] = Whr[l * 256 + h];
    }

    // ---- stage this batch row of x into smem ----
    for (int k = tid; k < TT; k += NTHREADS)
        xbuf[k] = x[b * TT + k];
    __syncthreads();

    float c0 = 0.0f, c1 = 0.0f;

    // ---- wavefront over supersteps: layer l handles t = s - l ----
    for (int s = 0; s < TT + LL - 1; ++s) {
        const int t = s - l;
        float* pprev = part + ((s - 1) & 1) * (LL * 4);

        if ((unsigned)t < (unsigned)TT) {
            float in;
            if (l == 0) {
                in = xbuf[t];
            } else {
                float* p = pprev + (l - 1) * 4;
                in = (p[0] + p[1]) + (p[2] + p[3]);
            }
            float hp = 0.0f;
            if (t > 0) {
                float* p = pprev + l * 4;
                hp = (p[0] + p[1]) + (p[2] + p[3]);
            }

            float acc;
            {   // channel 0
                float gi = fmaf(in, wI[0][0], fmaf(hp, wH[0][0], bS[0][0]));
                float gf = fmaf(in, wI[0][1], fmaf(hp, wH[0][1], bS[0][1]));
                float gg = fmaf(in, wI[0][2], fmaf(hp, wH[0][2], bS[0][2]));
                float go = fmaf(in, wI[0][3], fmaf(hp, wH[0][3], bS[0][3]));
                float i_ = fmaf(tanhapx(gi), 0.5f, 0.5f);
                float f_ = fmaf(tanhapx(gf), 0.5f, 0.5f);
                float g_ = tanhapx(gg);
                float o_ = fmaf(tanhapx(go), 0.5f, 0.5f);
                c0 = fmaf(f_, c0, i_ * g_);
                acc = (o_ * tanhapx(c0)) * wR[0];
            }
            {   // channel 1
                float gi = fmaf(in, wI[1][0], fmaf(hp, wH[1][0], bS[1][0]));
                float gf = fmaf(in, wI[1][1], fmaf(hp, wH[1][1], bS[1][1]));
                float gg = fmaf(in, wI[1][2], fmaf(hp, wH[1][2], bS[1][2]));
                float go = fmaf(in, wI[1][3], fmaf(hp, wH[1][3], bS[1][3]));
                float i_ = fmaf(tanhapx(gi), 0.5f, 0.5f);
                float f_ = fmaf(tanhapx(gf), 0.5f, 0.5f);
                float g_ = tanhapx(gg);
                float o_ = fmaf(tanhapx(go), 0.5f, 0.5f);
                c1 = fmaf(f_, c1, i_ * g_);
                acc = fmaf(o_ * tanhapx(c1), wR[1], acc);
            }
            // warp-wide reduce (128 threads/layer are 4 whole warps)
#pragma unroll
            for (int off = 16; off; off >>= 1)
                acc += __shfl_xor_sync(0xffffffffu, acc, off);
            if (lane == 0)
                part[(s & 1) * (LL * 4) + l * 4 + w] = acc;
        }

        // drain layer-4 output of superstep s-1 into hout
        if (tid == 0 && s >= 5) {
            float* p = pprev + 4 * 4;
            hout[s - 5] = (p[0] + p[1]) + (p[2] + p[3]);
        }
        __syncthreads();
    }
    if (tid == 0) {
        float* p = part + (((TT + LL - 2) & 1)) * (LL * 4) + 4 * 4;
        hout[TT - 1] = (p[0] + p[1]) + (p[2] + p[3]);
    }
    __syncthreads();

    // ---- MLP head: 1000 -> 100 (sig) -> 100 (sig) -> 100 (relu) -> 1 ----
    if (tid < 100) {
        const float* wrow = W1 + tid * 1000;
        float acc0 = 0.f, acc1 = 0.f, acc2 = 0.f, acc3 = 0.f;
#pragma unroll 2
        for (int k = 0; k < 1000; k += 4) {
            float4 wv = *(const float4*)(wrow + k);
            float4 hv = *(const float4*)(hout + k);
            acc0 = fmaf(wv.x, hv.x, acc0);
            acc1 = fmaf(wv.y, hv.y, acc1);
            acc2 = fmaf(wv.z, hv.z, acc2);
            acc3 = fmaf(wv.w, hv.w, acc3);
        }
        float acc = ((acc0 + acc1) + (acc2 + acc3)) + b1[tid];
        a1[tid] = 1.0f / (1.0f + expf(-acc));
    }
    __syncthreads();
    if (tid < 100) {
        const float* wrow = W2 + tid * 100;
        float acc = b2[tid];
#pragma unroll 4
        for (int k = 0; k < 100; ++k)
            acc = fmaf(wrow[k], a1[k], acc);
        a2[tid] = 1.0f / (1.0f + expf(-acc));
    }
    __syncthreads();
    if (tid < 100) {
        const float* wrow = W3 + tid * 100;
        float acc = b3[tid];
#pragma unroll 4
        for (int k = 0; k < 100; ++k)
            acc = fmaf(wrow[k], a2[k], acc);
        a3[tid] = fmaxf(acc, 0.0f);
    }
    __syncthreads();
    if (tid == 0) {
        float acc = b4[0];
#pragma unroll 4
        for (int k = 0; k < 100; ++k)
            acc = fmaf(W4[k], a3[k], acc);
        out[b] = acc;
    }
}

extern "C" void kernel_launch(void* const* d_in, const int* in_sizes, int n_in,
                              void* d_out, int out_size)
{
    const float* x   = (const float*)d_in[0];
    const float* Wih = (const float*)d_in[1];
    const float* Whh = (const float*)d_in[2];
    const float* bih = (const float*)d_in[3];
    const float* bhh = (const float*)d_in[4];
    const float* Whr = (const float*)d_in[5];
    const float* W1  = (const float*)d_in[6];
    const float* b1  = (const float*)d_in[7];
    const float* W2  = (const float*)d_in[8];
    const float* b2  = (const float*)d_in[9];
    const float* W3  = (const float*)d_in[10];
    const float* b3  = (const float*)d_in[11];
    const float* W4  = (const float*)d_in[12];
    const float* b4  = (const float*)d_in[13];
    float* out = (float*)d_out;

    lstm_wave_kernel<<<BBATCH, NTHREADS>>>(x, Wih, Whh, bih, bhh, Whr,
                                           W1, b1, W2, b2, W3, b3, W4, b4, out);
}

// round 3
// speedup vs baseline: 1.0301x; 1.0301x over previous
#include <cuda_runtime.h>
#include <math.h>

#define HH   256
#define LL   5
#define TT   1000
#define BBATCH 128
#define NTHREADS 640   // 128 threads per layer * 5 layers
#define DEPTH 64       // cross-layer ring depth (power of 2)

__device__ __forceinline__ float tanhapx(float x) {
    float r;
    asm("tanh.approx.f32 %0, %1;" : "=f"(r) : "f"(x));
    return r;
}

__device__ __forceinline__ float warp_reduce_add(float v) {
#pragma unroll
    for (int off = 16; off; off >>= 1)
        v += __shfl_xor_sync(0xffffffffu, v, off);
    return v;
}

__device__ __forceinline__ int ld_acquire(const int* p) {
    int v;
    asm volatile("ld.acquire.cta.b32 %0, [%1];" : "=r"(v) : "l"(p) : "memory");
    return v;
}

__device__ __forceinline__ void st_release(int* p, int v) {
    asm volatile("st.release.cta.b32 [%0], %1;" :: "l"(p), "r"(v) : "memory");
}

__global__ __launch_bounds__(NTHREADS, 1)
void lstm_async_kernel(const float* __restrict__ x,
                       const float* __restrict__ Wih,
                       const float* __restrict__ Whh,
                       const float* __restrict__ bih,
                       const float* __restrict__ bhh,
                       const float* __restrict__ Whr,
                       const float* __restrict__ W1,
                       const float* __restrict__ b1,
                       const float* __restrict__ W2,
                       const float* __restrict__ b2,
                       const float* __restrict__ W3,
                       const float* __restrict__ b3,
                       const float* __restrict__ W4,
                       const float* __restrict__ b4,
                       float* __restrict__ out)
{
    __shared__ __align__(16) float xbuf[TT];
    __shared__ __align__(16) float hout[TT];
    __shared__ float hring[LL][DEPTH];     // cross-layer h values
    __shared__ float part[LL][2][4];       // [layer][t&1][warp-in-layer]
    __shared__ int   prog[LL];             // last t published by layer l
    __shared__ volatile int cons[LL];      // last t consumed from layer l's ring
    __shared__ float a1[100], a2[100], a3[100];

    const int tid  = threadIdx.x;
    const int b    = blockIdx.x;
    const int l    = tid >> 7;        // layer: tid / 128
    const int j    = tid & 127;       // thread within layer
    const int w    = j >> 5;          // warp within layer (0..3)
    const int lane = j & 31;
    const int barid = l + 1;          // named barrier per layer

    // ---- load per-thread weights (2 channels x 4 gates) ----
    // gate order: i, f, g, o. sigmoid(x) = 0.5*tanh(0.5x)+0.5 -> fold 0.5 into
    // weights for gates i, f, o.
    float wI[2][4], wH[2][4], bS[2][4], wR[2];
#pragma unroll
    for (int ch = 0; ch < 2; ++ch) {
        int h = j + ch * 128;
#pragma unroll
        for (int g = 0; g < 4; ++g) {
            int idx = l * 1024 + g * 256 + h;
            float s = (g == 2) ? 1.0f : 0.5f;
            wI[ch][g] = Wih[idx] * s;
            wH[ch][g] = Whh[idx] * s;
            bS[ch][g] = (bih[idx] + bhh[idx]) * s;
        }
        wR[ch] = Whr[l * 256 + h];
    }

    // ---- stage this batch row of x into smem; init sync state ----
    for (int k = tid; k < TT; k += NTHREADS)
        xbuf[k] = x[b * TT + k];
    if (tid < LL) { prog[tid] = -1; cons[tid] = -1; }
    __syncthreads();

    float c0 = 0.0f, c1 = 0.0f;
    float hp = 0.0f;                 // own h(t-1), lives in a register

    for (int t = 0; t < TT; ++t) {
        // ---- acquire input ----
        float in;
        if (l == 0) {
            in = xbuf[t];
        } else {
            const int* pp = (const int*)&prog[l - 1];
            int p = ld_acquire(pp);
            while (p < t) { __nanosleep(20); p = ld_acquire(pp); }
            in = hring[l - 1][t & (DEPTH - 1)];
        }

        // ---- two channels of the LSTM cell ----
        float acc;
        {   // channel 0
            float gi = fmaf(in, wI[0][0], fmaf(hp, wH[0][0], bS[0][0]));
            float gf = fmaf(in, wI[0][1], fmaf(hp, wH[0][1], bS[0][1]));
            float gg = fmaf(in, wI[0][2], fmaf(hp, wH[0][2], bS[0][2]));
            float go = fmaf(in, wI[0][3], fmaf(hp, wH[0][3], bS[0][3]));
            float i_ = fmaf(tanhapx(gi), 0.5f, 0.5f);
            float f_ = fmaf(tanhapx(gf), 0.5f, 0.5f);
            float g_ = tanhapx(gg);
            float o_ = fmaf(tanhapx(go), 0.5f, 0.5f);
            c0 = fmaf(f_, c0, i_ * g_);
            acc = (o_ * tanhapx(c0)) * wR[0];
        }
        {   // channel 1
            float gi = fmaf(in, wI[1][0], fmaf(hp, wH[1][0], bS[1][0]));
            float gf = fmaf(in, wI[1][1], fmaf(hp, wH[1][1], bS[1][1]));
            float gg = fmaf(in, wI[1][2], fmaf(hp, wH[1][2], bS[1][2]));
            float go = fmaf(in, wI[1][3], fmaf(hp, wH[1][3], bS[1][3]));
            float i_ = fmaf(tanhapx(gi), 0.5f, 0.5f);
            float f_ = fmaf(tanhapx(gf), 0.5f, 0.5f);
            float g_ = tanhapx(gg);
            float o_ = fmaf(tanhapx(go), 0.5f, 0.5f);
            c1 = fmaf(f_, c1, i_ * g_);
            acc = fmaf(o_ * tanhapx(c1), wR[1], acc);
        }

        // ---- warp reduce + cross-warp combine within the layer ----
        acc = warp_reduce_add(acc);
        if (lane == 0)
            part[l][t & 1][w] = acc;
        asm volatile("bar.sync %0, 128;" :: "r"(barid) : "memory");

        const float* p4 = part[l][t & 1];
        float hs = (p4[0] + p4[1]) + (p4[2] + p4[3]);
        hp = hs;

        // ---- publish ----
        if (l < LL - 1) {
            if (j == 0) {
                if (t >= DEPTH) {                  // backpressure: slot reuse
                    while (cons[l] < t - DEPTH) __nanosleep(20);
                }
                hring[l][t & (DEPTH - 1)] = hs;
                st_release(&prog[l], t);
            }
        } else {
            if (j == 0) hout[t] = hs;
        }
        // mark layer (l-1)'s value at t fully consumed (post-bar: all 128
        // threads of this layer have read hring[l-1][t])
        if (l > 0 && j == 64) cons[l - 1] = t;
    }
    __syncthreads();

    // ---- MLP head: 1000 -> 100 (sig) -> 100 (sig) -> 100 (relu) -> 1 ----
    if (tid < 100) {
        const float* wrow = W1 + tid * 1000;
        float acc0 = 0.f, acc1 = 0.f, acc2 = 0.f, acc3 = 0.f;
#pragma unroll 2
        for (int k = 0; k < 1000; k += 4) {
            float4 wv = *(const float4*)(wrow + k);
            float4 hv = *(const float4*)(hout + k);
            acc0 = fmaf(wv.x, hv.x, acc0);
            acc1 = fmaf(wv.y, hv.y, acc1);
            acc2 = fmaf(wv.z, hv.z, acc2);
            acc3 = fmaf(wv.w, hv.w, acc3);
        }
        float acc = ((acc0 + acc1) + (acc2 + acc3)) + b1[tid];
        a1[tid] = 1.0f / (1.0f + expf(-acc));
    }
    __syncthreads();
    if (tid < 100) {
        const float* wrow = W2 + tid * 100;
        float acc = b2[tid];
#pragma unroll 4
        for (int k = 0; k < 100; ++k)
            acc = fmaf(wrow[k], a1[k], acc);
        a2[tid] = 1.0f / (1.0f + expf(-acc));
    }
    __syncthreads();
    if (tid < 100) {
        const float* wrow = W3 + tid * 100;
        float acc = b3[tid];
#pragma unroll 4
        for (int k = 0; k < 100; ++k)
            acc = fmaf(wrow[k], a2[k], acc);
        a3[tid] = fmaxf(acc, 0.0f);
    }
    __syncthreads();
    if (tid == 0) {
        float acc = b4[0];
#pragma unroll 4
        for (int k = 0; k < 100; ++k)
            acc = fmaf(W4[k], a3[k], acc);
        out[b] = acc;
    }
}

extern "C" void kernel_launch(void* const* d_in, const int* in_sizes, int n_in,
                              void* d_out, int out_size)
{
    const float* x   = (const float*)d_in[0];
    const float* Wih = (const float*)d_in[1];
    const float* Whh = (const float*)d_in[2];
    const float* bih = (const float*)d_in[3];
    const float* bhh = (const float*)d_in[4];
    const float* Whr = (const float*)d_in[5];
    const float* W1  = (const float*)d_in[6];
    const float* b1  = (const float*)d_in[7];
    const float* W2  = (const float*)d_in[8];
    const float* b2  = (const float*)d_in[9];
    const float* W3  = (const float*)d_in[10];
    const float* b3  = (const float*)d_in[11];
    const float* W4  = (const float*)d_in[12];
    const float* b4  = (const float*)d_in[13];
    float* out = (float*)d_out;

    lstm_async_kernel<<<BBATCH, NTHREADS>>>(x, Wih, Whh, bih, bhh, Whr,
                                            W1, b1, W2, b2, W3, b3, W4, b4, out);
}

// round 4
// speedup vs baseline: 1.3590x; 1.3193x over previous
#include <cuda_runtime.h>
#include <math.h>

#define HH   256
#define LL   5
#define TT   1000
#define BB   128

typedef unsigned long long ull;

// Cross-layer mailboxes: one 8-byte {tag=t+1, value} slot per (layer, batch, t).
// Written exactly once per launch; tags zeroed by reset kernel each launch.
__device__ ull   g_mbox[LL - 1][BB][TT];   // 4.096 MB
__device__ float g_hseq[BB][TT];           // layer-4 outputs, 512 KB

__device__ __forceinline__ float tanhapx(float x) {
    float r;
    asm("tanh.approx.f32 %0, %1;" : "=f"(r) : "f"(x));
    return r;
}

__device__ __forceinline__ int redux_s32(int v) {
    int r;
    asm volatile("redux.sync.add.s32 %0, %1, 0xffffffff;" : "=r"(r) : "r"(v));
    return r;
}

// ---------------------------------------------------------------- reset
__global__ void reset_mbox_kernel() {
    ull* p = &g_mbox[0][0][0];
    const int n = (LL - 1) * BB * TT;
    for (int i = blockIdx.x * blockDim.x + threadIdx.x; i < n;
         i += gridDim.x * blockDim.x)
        p[i] = 0ull;
}

// ---------------------------------------------------------------- LSTM pipeline
// grid = LL*BB blocks of 128 threads; block (l, b) runs layer l of batch b.
__global__ void __launch_bounds__(128)
lstm_layer_kernel(const float* __restrict__ x,
                  const float* __restrict__ Wih,
                  const float* __restrict__ Whh,
                  const float* __restrict__ bih,
                  const float* __restrict__ bhh,
                  const float* __restrict__ Whr)
{
    __shared__ __align__(16) float xbuf[TT];
    __shared__ __align__(16) int   part[2][4];

    const int tid = threadIdx.x;
    const int l   = blockIdx.x >> 7;      // layer
    const int b   = blockIdx.x & 127;     // batch element
    const int w   = tid >> 5;
    const int lane = tid & 31;

    // ---- per-thread weights: 2 channels x 4 gates ----
    // gate order i,f,g,o; sigmoid(x)=0.5*tanh(0.5x)+0.5 with 0.5 folded in.
    float wI[2][4], wH[2][4], bS[2][4], wR[2];
#pragma unroll
    for (int ch = 0; ch < 2; ++ch) {
        int h = tid + ch * 128;
#pragma unroll
        for (int g = 0; g < 4; ++g) {
            int idx = l * 1024 + g * 256 + h;
            float s = (g == 2) ? 1.0f : 0.5f;
            wI[ch][g] = Wih[idx] * s;
            wH[ch][g] = Whh[idx] * s;
            bS[ch][g] = (bih[idx] + bhh[idx]) * s;
        }
        wR[ch] = Whr[l * 256 + h];
    }

    if (l == 0) {
        for (int k = tid; k < TT; k += 128)
            xbuf[k] = x[b * TT + k];
    }
    __syncthreads();

    const ull* mb_in  = (l > 0) ? g_mbox[l - 1][b] : (const ull*)0;
    ull*       mb_out = (l < LL - 1) ? g_mbox[l][b] : (ull*)0;

    float c0 = 0.0f, c1 = 0.0f;
    float hp = 0.0f;
    ull pre = 0ull;
    if (l > 0) pre = *(volatile const ull*)mb_in;   // prefetch slot 0

    for (int t = 0; t < TT; ++t) {
        // ---- obtain input (register-resident in steady state) ----
        float in;
        if (l == 0) {
            in = xbuf[t];
        } else {
            ull v = pre;
            const unsigned want = (unsigned)(t + 1);
            while ((unsigned)(v >> 32) != want)
                v = *(volatile const ull*)(mb_in + t);
            in = __uint_as_float((unsigned)v);
            if (t + 1 < TT)                          // prefetch next slot;
                pre = *(volatile const ull*)(mb_in + t + 1);  // overlaps compute
        }

        // ---- two channels of the LSTM cell (f32) ----
        float acc;
        {   // channel 0
            float gi = fmaf(in, wI[0][0], fmaf(hp, wH[0][0], bS[0][0]));
            float gf = fmaf(in, wI[0][1], fmaf(hp, wH[0][1], bS[0][1]));
            float gg = fmaf(in, wI[0][2], fmaf(hp, wH[0][2], bS[0][2]));
            float go = fmaf(in, wI[0][3], fmaf(hp, wH[0][3], bS[0][3]));
            float i_ = fmaf(tanhapx(gi), 0.5f, 0.5f);
            float f_ = fmaf(tanhapx(gf), 0.5f, 0.5f);
            float g_ = tanhapx(gg);
            float o_ = fmaf(tanhapx(go), 0.5f, 0.5f);
            c0 = fmaf(f_, c0, i_ * g_);
            acc = (o_ * tanhapx(c0)) * wR[0];
        }
        {   // channel 1
            float gi = fmaf(in, wI[1][0], fmaf(hp, wH[1][0], bS[1][0]));
            float gf = fmaf(in, wI[1][1], fmaf(hp, wH[1][1], bS[1][1]));
            float gg = fmaf(in, wI[1][2], fmaf(hp, wH[1][2], bS[1][2]));
            float go = fmaf(in, wI[1][3], fmaf(hp, wH[1][3], bS[1][3]));
            float i_ = fmaf(tanhapx(gi), 0.5f, 0.5f);
            float f_ = fmaf(tanhapx(gf), 0.5f, 0.5f);
            float g_ = tanhapx(gg);
            float o_ = fmaf(tanhapx(go), 0.5f, 0.5f);
            c1 = fmaf(f_, c1, i_ * g_);
            acc = fmaf(o_ * tanhapx(c1), wR[1], acc);
        }

        // ---- reduce 256 channels: fixed-point warp redux + 4-warp combine ----
        int q = __float2int_rn(acc * 16777216.0f);          // 2^24
        int r = redux_s32(q);
        if (lane == 0) part[t & 1][w] = r;
        __syncthreads();
        const int* p4 = part[t & 1];
        int hi = (p4[0] + p4[1]) + (p4[2] + p4[3]);
        hp = (float)hi * 5.9604644775390625e-8f;            // 2^-24

        // ---- publish ----
        if (tid == 0) {
            if (mb_out) {
                ull v = ((ull)(unsigned)(t + 1) << 32) |
                        (ull)__float_as_uint(hp);
                *(volatile ull*)(mb_out + t) = v;
            } else {
                g_hseq[b][t] = hp;
            }
        }
    }
}

// ---------------------------------------------------------------- MLP head
__global__ void __launch_bounds__(128)
mlp_kernel(const float* __restrict__ W1, const float* __restrict__ b1,
           const float* __restrict__ W2, const float* __restrict__ b2,
           const float* __restrict__ W3, const float* __restrict__ b3,
           const float* __restrict__ W4, const float* __restrict__ b4,
           float* __restrict__ out)
{
    __shared__ __align__(16) float hbuf[TT];
    __shared__ float a1[100], a2[100], a3[100];

    const int tid = threadIdx.x;
    const int b   = blockIdx.x;

    for (int k = tid; k < TT; k += 128)
        hbuf[k] = g_hseq[b][k];
    __syncthreads();

    if (tid < 100) {
        const float* wrow = W1 + tid * 1000;
        float acc0 = 0.f, acc1 = 0.f, acc2 = 0.f, acc3 = 0.f;
#pragma unroll 2
        for (int k = 0; k < 1000; k += 4) {
            float4 wv = *(const float4*)(wrow + k);
            float4 hv = *(const float4*)(hbuf + k);
            acc0 = fmaf(wv.x, hv.x, acc0);
            acc1 = fmaf(wv.y, hv.y, acc1);
            acc2 = fmaf(wv.z, hv.z, acc2);
            acc3 = fmaf(wv.w, hv.w, acc3);
        }
        float acc = ((acc0 + acc1) + (acc2 + acc3)) + b1[tid];
        a1[tid] = 1.0f / (1.0f + expf(-acc));
    }
    __syncthreads();
    if (tid < 100) {
        const float* wrow = W2 + tid * 100;
        float acc = b2[tid];
#pragma unroll 4
        for (int k = 0; k < 100; ++k)
            acc = fmaf(wrow[k], a1[k], acc);
        a2[tid] = 1.0f / (1.0f + expf(-acc));
    }
    __syncthreads();
    if (tid < 100) {
        const float* wrow = W3 + tid * 100;
        float acc = b3[tid];
#pragma unroll 4
        for (int k = 0; k < 100; ++k)
            acc = fmaf(wrow[k], a2[k], acc);
        a3[tid] = fmaxf(acc, 0.0f);
    }
    __syncthreads();
    if (tid == 0) {
        float acc = b4[0];
#pragma unroll 4
        for (int k = 0; k < 100; ++k)
            acc = fmaf(W4[k], a3[k], acc);
        out[b] = acc;
    }
}

extern "C" void kernel_launch(void* const* d_in, const int* in_sizes, int n_in,
                              void* d_out, int out_size)
{
    const float* x   = (const float*)d_in[0];
    const float* Wih = (const float*)d_in[1];
    const float* Whh = (const float*)d_in[2];
    const float* bih = (const float*)d_in[3];
    const float* bhh = (const float*)d_in[4];
    const float* Whr = (const float*)d_in[5];
    const float* W1  = (const float*)d_in[6];
    const float* b1  = (const float*)d_in[7];
    const float* W2  = (const float*)d_in[8];
    const float* b2  = (const float*)d_in[9];
    const float* W3  = (const float*)d_in[10];
    const float* b3  = (const float*)d_in[11];
    const float* W4  = (const float*)d_in[12];
    const float* b4  = (const float*)d_in[13];
    float* out = (float*)d_out;

    reset_mbox_kernel<<<256, 256>>>();
    lstm_layer_kernel<<<LL * BB, 128>>>(x, Wih, Whh, bih, bhh, Whr);
    mlp_kernel<<<BB, 128>>>(W1, b1, W2, b2, W3, b3, W4, b4, out);
}